// round 15
// baseline (speedup 1.0000x reference)
#include <cuda_runtime.h>
#include <cuda_fp16.h>
#include <math.h>
#include <stdint.h>

// Problem constants
#define B_ 4
#define N_ 96
#define P_ 64
#define C_ 1024
#define H_ 16
#define HD_ 64
#define M_ROWS (B_*N_*P_)   // 24576
#define MB (N_*P_)          // 6144 rows per batch

// Scratch (device globals: allocation-free contract)
__device__ __half  g_xh[M_ROWS*C_];       // x, fp16
__device__ __half  g_xbar[B_*N_*C_];      // pooled input, fp16
__device__ float   g_qk[B_*N_*2*C_];      // q|k projections (fp32)
__device__ __half  g_attnh[B_*H_*N_*N_];  // softmax probs, fp16
__device__ __half  g_vh[M_ROWS*C_];       // x @ W_v, fp16
__device__ __half  g_oh[M_ROWS*C_];       // attn-applied, fp16
__device__ __half  g_wqkt[2*C_*C_];       // W_qk^T [n][k], fp16
__device__ __half  g_wvt[C_*C_];          // W_v^T
__device__ __half  g_wpt[C_*C_];          // W_proj^T

#define LDSM4(R0,R1,R2,R3,ADDR) \
    asm volatile("ldmatrix.sync.aligned.m8n8.x4.shared.b16 {%0,%1,%2,%3}, [%4];" \
        : "=r"(R0),"=r"(R1),"=r"(R2),"=r"(R3) : "r"(ADDR))
#define LDSM4T(R0,R1,R2,R3,ADDR) \
    asm volatile("ldmatrix.sync.aligned.m8n8.x4.trans.shared.b16 {%0,%1,%2,%3}, [%4];" \
        : "=r"(R0),"=r"(R1),"=r"(R2),"=r"(R3) : "r"(ADDR))

#define MMA_F16(C0,C1,C2,C3,A0,A1,A2,A3,B0,B1) \
    asm volatile("mma.sync.aligned.m16n8k16.row.col.f32.f16.f16.f32 " \
        "{%0,%1,%2,%3}, {%4,%5,%6,%7}, {%8,%9}, {%0,%1,%2,%3};" \
        : "+f"(C0),"+f"(C1),"+f"(C2),"+f"(C3) \
        : "r"(A0),"r"(A1),"r"(A2),"r"(A3),"r"(B0),"r"(B1))

#define CP16(DST, SRC) \
    asm volatile("cp.async.cg.shared.global [%0], [%1], 16;" :: "r"(DST), "l"(SRC) : "memory")
#define CP_COMMIT() asm volatile("cp.async.commit_group;" ::: "memory")
#define CP_WAIT1()  asm volatile("cp.async.wait_group 1;" ::: "memory")

// ---------------------------------------------------------------------------
// FP16 tensor GEMM v3: C = A[M,K] @ Bt[N,K]^T (+bias), fp32 accum.
// CTA tile 192x128, 128 threads (4 warps: 2M x 2N), warp tile 96x64, KTILE=32,
// 3-stage cp.async. 75 KB smem, <=256 regs -> 2 CTAs/SM.
// ldsm:HMMA wavefront ratio 0.83 (tensor-bound; was 1.0).
// ---------------------------------------------------------------------------
#define SROW16 40                           // halves per smem row
#define TA16 (192 * SROW16 * 2)             // 15360 B
#define TB16 (128 * SROW16 * 2)             // 10240 B
#define ST16 (TA16 + TB16)                  // 25600 B
#define NST 3
#define TC_SMEM (NST * ST16)                // 76800 B

__global__ void __launch_bounds__(128, 2) tc_gemm(
    const __half* __restrict__ A, const __half* __restrict__ Bt,
    void* __restrict__ Cm, const float* __restrict__ bias,
    int K, int lda, int ldb, int ldc, int outHalf)
{
    extern __shared__ char smem[];
    uint32_t smem_base = (uint32_t)__cvta_generic_to_shared(smem);
    int tid = threadIdx.x;
    int lane = tid & 31, warp = tid >> 5;
    int wm = warp & 1, wn = warp >> 1;

    const __half* Ab = A + (size_t)blockIdx.y * 192 * lda;
    const __half* Bb = Bt + (size_t)blockIdx.x * 128 * ldb;

    float acc[6][8][4];
    #pragma unroll
    for (int i = 0; i < 6; ++i)
        #pragma unroll
        for (int j = 0; j < 8; ++j)
            #pragma unroll
            for (int r = 0; r < 4; ++r) acc[i][j][r] = 0.f;

    auto load_stage = [&](int s, int kt) {
        uint32_t sa = smem_base + s * ST16;
        uint32_t sb = sa + TA16;
        #pragma unroll
        for (int it = 0; it < 6; ++it) {          // A: 768 x 16B
            int q = tid + it * 128;
            int r = q >> 2, c = q & 3;
            CP16(sa + (uint32_t)(r * SROW16 + c * 8) * 2u,
                 Ab + (size_t)r * lda + kt * 32 + c * 8);
        }
        #pragma unroll
        for (int it = 0; it < 4; ++it) {          // B: 512 x 16B
            int q = tid + it * 128;
            int r = q >> 2, c = q & 3;
            CP16(sb + (uint32_t)(r * SROW16 + c * 8) * 2u,
                 Bb + (size_t)r * ldb + kt * 32 + c * 8);
        }
    };

    int nt = K / 32;
    load_stage(0, 0); CP_COMMIT();
    load_stage(1, 1); CP_COMMIT();

    int l7 = lane & 7;
    int lg8 = (lane >> 3) & 1;
    int lg16 = lane >> 4;

    #pragma unroll 1
    for (int kt = 0; kt < nt; ++kt) {
        CP_WAIT1();
        __syncthreads();
        if (kt + 2 < nt) load_stage((kt + 2) % NST, kt + 2);
        CP_COMMIT();

        uint32_t sa = smem_base + (kt % NST) * ST16;
        uint32_t sb = sa + TA16;

        #pragma unroll
        for (int ks = 0; ks < 2; ++ks) {
            int k0 = ks * 16;
            uint32_t a[6][4], b[4][4];
            #pragma unroll
            for (int mi = 0; mi < 6; ++mi) {
                int row = wm * 96 + mi * 16 + l7 + lg8 * 8;
                int kc = k0 + lg16 * 8;
                LDSM4(a[mi][0], a[mi][1], a[mi][2], a[mi][3],
                      sa + (uint32_t)(row * SROW16 + kc) * 2u);
            }
            #pragma unroll
            for (int pi = 0; pi < 4; ++pi) {
                int nrow = wn * 64 + pi * 16 + l7 + lg16 * 8;
                int kc = k0 + lg8 * 8;
                LDSM4(b[pi][0], b[pi][1], b[pi][2], b[pi][3],
                      sb + (uint32_t)(nrow * SROW16 + kc) * 2u);
            }
            #pragma unroll
            for (int mi = 0; mi < 6; ++mi)
                #pragma unroll
                for (int ni = 0; ni < 8; ++ni)
                    MMA_F16(acc[mi][ni][0], acc[mi][ni][1], acc[mi][ni][2], acc[mi][ni][3],
                            a[mi][0], a[mi][1], a[mi][2], a[mi][3],
                            b[ni >> 1][(ni & 1) * 2], b[ni >> 1][(ni & 1) * 2 + 1]);
        }
    }

    int cm = blockIdx.y * 192 + wm * 96;
    int cn = blockIdx.x * 128 + wn * 64;
    int er = lane >> 2;
    int ec = (lane & 3) * 2;
    #pragma unroll
    for (int ni = 0; ni < 8; ++ni) {
        int col = cn + ni * 8 + ec;
        float bb0 = bias ? bias[col] : 0.f;
        float bb1 = bias ? bias[col + 1] : 0.f;
        #pragma unroll
        for (int mi = 0; mi < 6; ++mi) {
            int row = cm + mi * 16 + er;
            float v0 = acc[mi][ni][0] + bb0, v1 = acc[mi][ni][1] + bb1;
            float v2 = acc[mi][ni][2] + bb0, v3 = acc[mi][ni][3] + bb1;
            if (outHalf) {
                __half* Ch = (__half*)Cm;
                *(__half2*)(Ch + (size_t)row * ldc + col) = __floats2half2_rn(v0, v1);
                *(__half2*)(Ch + (size_t)(row + 8) * ldc + col) = __floats2half2_rn(v2, v3);
            } else {
                float* Cf = (float*)Cm;
                *(float2*)(Cf + (size_t)row * ldc + col) = make_float2(v0, v1);
                *(float2*)(Cf + (size_t)(row + 8) * ldc + col) = make_float2(v2, v3);
            }
        }
    }
}

// ---------------------------------------------------------------------------
// apply_tc v2: per (b,h) GEMM  o[n,(p,hd)] = attn[n,m] @ v[m,(p,hd)].
// 128 threads (4 warps: 2M x 2N), CTA 96x128, warp tile 48x64, K=96.
// wf:HMMA 1.17 (was 1.67); 27 KB smem -> multiple CTAs/SM.
// ---------------------------------------------------------------------------
#define AP_AROW 24
#define AP_BROW 136
#define AP_TA (96 * AP_AROW * 2)
#define AP_TB (16 * AP_BROW * 2)
#define AP_ST (AP_TA + AP_TB)
#define AP_SMEM (3 * AP_ST)             // 26880 B

__global__ void __launch_bounds__(128) apply_tc(
    const __half* __restrict__ v, const __half* __restrict__ attn,
    __half* __restrict__ out, int bArg)
{
    extern __shared__ char smem[];
    uint32_t smem_base = (uint32_t)__cvta_generic_to_shared(smem);
    int tid = threadIdx.x;
    int lane = tid & 31, warp = tid >> 5;
    int wm = warp & 1, wn = warp >> 1;

    int h = blockIdx.y;
    int b = bArg;
    int bh = b * H_ + h;
    int p0 = blockIdx.x * 2;

    const __half* ab = attn + (size_t)bh * N_ * N_;
    const __half* vb = v + (size_t)b * N_ * P_ * C_ + h * HD_;

    float acc[3][8][4];
    #pragma unroll
    for (int i = 0; i < 3; ++i)
        #pragma unroll
        for (int j = 0; j < 8; ++j)
            #pragma unroll
            for (int r = 0; r < 4; ++r) acc[i][j][r] = 0.f;

    auto load_stage = [&](int s, int kt) {
        uint32_t sa = smem_base + s * AP_ST;
        uint32_t sb = sa + AP_TA;
        // A: 96 rows x 2 chunks = 192
        #pragma unroll
        for (int it = 0; it < 2; ++it) {
            int q = tid + it * 128;
            if (q < 192) {
                int r = q >> 1, c = q & 1;
                CP16(sa + (uint32_t)(r * AP_AROW + c * 8) * 2u,
                     ab + (size_t)r * N_ + kt * 16 + c * 8);
            }
        }
        // B: 16 k-rows x 16 chunks = 256
        #pragma unroll
        for (int it = 0; it < 2; ++it) {
            int q = tid + it * 128;
            int r = q >> 4, c = q & 15;
            int m = kt * 16 + r;
            int p = p0 + (c >> 3), hd = (c & 7) * 8;
            CP16(sb + (uint32_t)(r * AP_BROW + c * 8) * 2u,
                 vb + (size_t)m * P_ * C_ + (size_t)p * C_ + hd);
        }
    };

    load_stage(0, 0); CP_COMMIT();
    load_stage(1, 1); CP_COMMIT();

    int l7 = lane & 7;
    int lg8 = (lane >> 3) & 1;
    int lg16 = lane >> 4;

    #pragma unroll 1
    for (int kt = 0; kt < 6; ++kt) {
        CP_WAIT1();
        __syncthreads();
        if (kt + 2 < 6) load_stage((kt + 2) % 3, kt + 2);
        CP_COMMIT();

        uint32_t sa = smem_base + (kt % 3) * AP_ST;
        uint32_t sb = sa + AP_TA;

        uint32_t a[3][4], bfr[4][4];
        #pragma unroll
        for (int mi = 0; mi < 3; ++mi) {
            int row = wm * 48 + mi * 16 + l7 + lg8 * 8;
            int kc = lg16 * 8;
            LDSM4(a[mi][0], a[mi][1], a[mi][2], a[mi][3],
                  sa + (uint32_t)(row * AP_AROW + kc) * 2u);
        }
        #pragma unroll
        for (int pi = 0; pi < 4; ++pi) {
            int krow = l7 + lg8 * 8;
            int nc = wn * 64 + pi * 16 + lg16 * 8;
            LDSM4T(bfr[pi][0], bfr[pi][1], bfr[pi][2], bfr[pi][3],
                   sb + (uint32_t)(krow * AP_BROW + nc) * 2u);
        }
        #pragma unroll
        for (int mi = 0; mi < 3; ++mi)
            #pragma unroll
            for (int ni = 0; ni < 8; ++ni)
                MMA_F16(acc[mi][ni][0], acc[mi][ni][1], acc[mi][ni][2], acc[mi][ni][3],
                        a[mi][0], a[mi][1], a[mi][2], a[mi][3],
                        bfr[ni >> 1][(ni & 1) * 2], bfr[ni >> 1][(ni & 1) * 2 + 1]);
    }

    int er = lane >> 2;
    int ec = (lane & 3) * 2;
    #pragma unroll
    for (int ni = 0; ni < 8; ++ni) {
        int col = wn * 64 + ni * 8 + ec;
        int p = p0 + (col >> 6), hd = col & 63;
        #pragma unroll
        for (int mi = 0; mi < 3; ++mi) {
            int n = wm * 48 + mi * 16 + er;
            __half* op = out + (((size_t)(b * N_ + n) * P_) + p) * C_ + h * HD_ + hd;
            *(__half2*)op = __floats2half2_rn(acc[mi][ni][0], acc[mi][ni][1]);
            __half* op2 = out + (((size_t)(b * N_ + n + 8) * P_) + p) * C_ + h * HD_ + hd;
            *(__half2*)op2 = __floats2half2_rn(acc[mi][ni][2], acc[mi][ni][3]);
        }
    }
}

// ---------------------------------------------------------------------------
// Weight transpose + fp16: Wt[n][k] = h(W[k][n]); output ld = 1024
// ---------------------------------------------------------------------------
__global__ void wtrans_kernel(const float* __restrict__ W, __half* __restrict__ Wt, int ldw) {
    __shared__ float t[32][33];
    int n0 = blockIdx.x * 32, k0 = blockIdx.y * 32;
    int tx = threadIdx.x, ty = threadIdx.y;
    #pragma unroll
    for (int i = 0; i < 32; i += 8)
        t[ty + i][tx] = W[(size_t)(k0 + ty + i) * ldw + n0 + tx];
    __syncthreads();
    #pragma unroll
    for (int i = 0; i < 32; i += 8)
        Wt[(size_t)(n0 + ty + i) * C_ + k0 + tx] = __float2half_rn(t[tx][ty + i]);
}

// ---------------------------------------------------------------------------
// prep: fused cvt + pool for ONE batch. Block = one n (96 blocks), 256 threads.
// ---------------------------------------------------------------------------
__global__ void __launch_bounds__(256) prep_kernel(
    const float* __restrict__ x, __half* __restrict__ xh,
    __half* __restrict__ xbar, int bArg)
{
    int bn = bArg * N_ + blockIdx.x;
    const float* xp = x + (size_t)bn * P_ * C_;
    __half* xhp = xh + (size_t)bn * P_ * C_;
    int c = threadIdx.x * 4;
    float s0 = 0.f, s1 = 0.f, s2 = 0.f, s3 = 0.f;
    #pragma unroll 4
    for (int p = 0; p < P_; ++p) {
        float4 v = *(const float4*)(xp + (size_t)p * C_ + c);
        s0 += v.x; s1 += v.y; s2 += v.z; s3 += v.w;
        *(__half2*)(xhp + (size_t)p * C_ + c)     = __floats2half2_rn(v.x, v.y);
        *(__half2*)(xhp + (size_t)p * C_ + c + 2) = __floats2half2_rn(v.z, v.w);
    }
    __half* xb = xbar + (size_t)bn * C_ + c;
    *(__half2*)xb       = __floats2half2_rn(s0 * (1.f / 64.f), s1 * (1.f / 64.f));
    *(__half2*)(xb + 2) = __floats2half2_rn(s2 * (1.f / 64.f), s3 * (1.f / 64.f));
}

// ---------------------------------------------------------------------------
// attn: block=(b,h), 256 threads; warp per n-row, shfl softmax.
// ---------------------------------------------------------------------------
#define ATTN_SMEM (96*64*4 + 64*96*4)   // 49152
__global__ void __launch_bounds__(256) attn_kernel(
    const float* __restrict__ qk, __half* __restrict__ attn)
{
    extern __shared__ float sm[];
    float* qs = sm;               // [96][64]
    float* kt = sm + 96 * 64;     // [64][96]
    int b = blockIdx.x >> 4, h = blockIdx.x & 15;
    for (int i = threadIdx.x; i < N_ * HD_; i += 256) {
        int n = i >> 6, d = i & 63;
        const float* base = qk + ((size_t)(b * N_ + n)) * (2 * C_) + h * HD_ + d;
        qs[n * HD_ + d] = base[0];
        kt[d * N_ + n] = base[C_];
    }
    __syncthreads();

    int warp = threadIdx.x >> 5, lane = threadIdx.x & 31;
    int m0 = lane * 3;
    for (int n = warp; n < N_; n += 8) {
        float d0 = 0.f, d1 = 0.f, d2 = 0.f;
        const float* qr = qs + n * HD_;
        #pragma unroll
        for (int d = 0; d < HD_; ++d) {
            float q = qr[d];
            const float* kr = kt + d * N_ + m0;
            d0 += q * kr[0]; d1 += q * kr[1]; d2 += q * kr[2];
        }
        d0 *= 0.125f; d1 *= 0.125f; d2 *= 0.125f;
        float mx = fmaxf(d0, fmaxf(d1, d2));
        #pragma unroll
        for (int o = 16; o; o >>= 1) mx = fmaxf(mx, __shfl_xor_sync(0xFFFFFFFFu, mx, o));
        float e0 = __expf(d0 - mx), e1 = __expf(d1 - mx), e2 = __expf(d2 - mx);
        float s = e0 + e1 + e2;
        #pragma unroll
        for (int o = 16; o; o >>= 1) s += __shfl_xor_sync(0xFFFFFFFFu, s, o);
        float inv = 1.f / s;
        __half* row = attn + ((size_t)blockIdx.x * N_ + n) * N_ + m0;
        row[0] = __float2half_rn(e0 * inv);
        row[1] = __float2half_rn(e1 * inv);
        row[2] = __float2half_rn(e2 * inv);
    }
}

// ---------------------------------------------------------------------------
extern "C" void kernel_launch(void* const* d_in, const int* in_sizes, int n_in,
                              void* d_out, int out_size)
{
    const float* x     = (const float*)d_in[0];
    const float* Wqkv  = (const float*)d_in[1];
    const float* Wproj = (const float*)d_in[2];
    const float* bproj = (const float*)d_in[3];
    float* out = (float*)d_out;

    __half *xh, *xbar, *attnbuf, *vbuf, *obuf, *wqkt, *wvt, *wpt;
    float *qkbuf;
    cudaGetSymbolAddress((void**)&xh,      g_xh);
    cudaGetSymbolAddress((void**)&xbar,    g_xbar);
    cudaGetSymbolAddress((void**)&qkbuf,   g_qk);
    cudaGetSymbolAddress((void**)&attnbuf, g_attnh);
    cudaGetSymbolAddress((void**)&vbuf,    g_vh);
    cudaGetSymbolAddress((void**)&obuf,    g_oh);
    cudaGetSymbolAddress((void**)&wqkt,    g_wqkt);
    cudaGetSymbolAddress((void**)&wvt,     g_wvt);
    cudaGetSymbolAddress((void**)&wpt,     g_wpt);

    cudaFuncSetAttribute(tc_gemm, cudaFuncAttributeMaxDynamicSharedMemorySize, TC_SMEM);
    cudaFuncSetAttribute(apply_tc, cudaFuncAttributeMaxDynamicSharedMemorySize, AP_SMEM);
    cudaFuncSetAttribute(attn_kernel, cudaFuncAttributeMaxDynamicSharedMemorySize, ATTN_SMEM);

    // Streams + events (created once; host-side only).
    static cudaStream_t s2 = nullptr, s3 = nullptr, s4 = nullptr;
    static cudaEvent_t evRoot, evAttn, evWpt, evWvt, evP0, evP2, evP3, evB1, evB2, evB3;
    if (!s2) {
        cudaStreamCreateWithFlags(&s2, cudaStreamNonBlocking);
        cudaStreamCreateWithFlags(&s3, cudaStreamNonBlocking);
        cudaStreamCreateWithFlags(&s4, cudaStreamNonBlocking);
        cudaEventCreateWithFlags(&evRoot, cudaEventDisableTiming);
        cudaEventCreateWithFlags(&evAttn, cudaEventDisableTiming);
        cudaEventCreateWithFlags(&evWpt, cudaEventDisableTiming);
        cudaEventCreateWithFlags(&evWvt, cudaEventDisableTiming);
        cudaEventCreateWithFlags(&evP0, cudaEventDisableTiming);
        cudaEventCreateWithFlags(&evP2, cudaEventDisableTiming);
        cudaEventCreateWithFlags(&evP3, cudaEventDisableTiming);
        cudaEventCreateWithFlags(&evB1, cudaEventDisableTiming);
        cudaEventCreateWithFlags(&evB2, cudaEventDisableTiming);
        cudaEventCreateWithFlags(&evB3, cudaEventDisableTiming);
    }

    // ---- Capture-safe ordering: every record precedes every wait on it.

    cudaEventRecord(evRoot, 0);
    cudaStreamWaitEvent(s2, evRoot, 0);
    cudaStreamWaitEvent(s3, evRoot, 0);
    cudaStreamWaitEvent(s4, evRoot, 0);

    const size_t off1 = (size_t)1 * MB * C_;
    const size_t off2 = (size_t)2 * MB * C_;
    const size_t off3 = (size_t)3 * MB * C_;

    // Prologue phase --------------------------------------------------------
    // main: batch-0 prep only (critical path minimal)
    prep_kernel<<<N_, 256>>>(x, xh, xbar, 0);
    cudaEventRecord(evP0, 0);
    // s4: v-weight transpose + batch-3 prep
    wtrans_kernel<<<dim3(32, 32), dim3(32, 8), 0, s4>>>(Wqkv + 2 * C_, wvt, 3 * C_);
    cudaEventRecord(evWvt, s4);
    prep_kernel<<<N_, 256, 0, s4>>>(x, xh, xbar, 3);
    cudaEventRecord(evP3, s4);
    // s3: proj-weight transpose + batch-2 prep
    wtrans_kernel<<<dim3(32, 32), dim3(32, 8), 0, s3>>>(Wproj, wpt, C_);
    cudaEventRecord(evWpt, s3);
    prep_kernel<<<N_, 256, 0, s3>>>(x, xh, xbar, 2);
    cudaEventRecord(evP2, s3);
    // s2: qk-weight transpose + batch-1 prep, then qk/attn (needs all xbar)
    wtrans_kernel<<<dim3(64, 32), dim3(32, 8), 0, s2>>>(Wqkv, wqkt, 3 * C_);
    prep_kernel<<<N_, 256, 0, s2>>>(x, xh, xbar, 1);
    cudaStreamWaitEvent(s2, evP0, 0);
    cudaStreamWaitEvent(s2, evP2, 0);
    cudaStreamWaitEvent(s2, evP3, 0);
    tc_gemm<<<dim3(16, 2), 128, TC_SMEM, s2>>>(xbar, wqkt, qkbuf, nullptr, 1024, C_, C_, 2 * C_, 0);
    attn_kernel<<<B_ * H_, 256, ATTN_SMEM, s2>>>(qkbuf, attnbuf);
    cudaEventRecord(evAttn, s2);

    // Pipeline phase --------------------------------------------------------
    // main: batch 0 (xh0 on this stream; needs wvt, attn, wpt)
    cudaStreamWaitEvent(0, evWvt, 0);
    tc_gemm<<<dim3(8, 32), 128, TC_SMEM>>>(xh, wvt, vbuf, nullptr, 1024, C_, C_, C_, 1);
    cudaStreamWaitEvent(0, evAttn, 0);
    apply_tc<<<dim3(32, 16), 128, AP_SMEM>>>(vbuf, attnbuf, obuf, 0);
    cudaStreamWaitEvent(0, evWpt, 0);
    tc_gemm<<<dim3(8, 32), 128, TC_SMEM>>>(obuf, wpt, out, bproj, 1024, C_, C_, C_, 0);

    // s2: batch 1 (xh1 + attn on this stream; needs wvt + wpt)
    cudaStreamWaitEvent(s2, evWvt, 0);
    tc_gemm<<<dim3(8, 32), 128, TC_SMEM, s2>>>(xh + off1, wvt, vbuf + off1, nullptr,
                                               1024, C_, C_, C_, 1);
    apply_tc<<<dim3(32, 16), 128, AP_SMEM, s2>>>(vbuf, attnbuf, obuf, 1);
    cudaStreamWaitEvent(s2, evWpt, 0);
    tc_gemm<<<dim3(8, 32), 128, TC_SMEM, s2>>>(obuf + off1, wpt, out + off1, bproj,
                                               1024, C_, C_, C_, 0);
    cudaEventRecord(evB1, s2);

    // s3: batch 2 (xh2 + wpt on this stream; needs wvt + attn)
    cudaStreamWaitEvent(s3, evWvt, 0);
    tc_gemm<<<dim3(8, 32), 128, TC_SMEM, s3>>>(xh + off2, wvt, vbuf + off2, nullptr,
                                               1024, C_, C_, C_, 1);
    cudaStreamWaitEvent(s3, evAttn, 0);
    apply_tc<<<dim3(32, 16), 128, AP_SMEM, s3>>>(vbuf, attnbuf, obuf, 2);
    tc_gemm<<<dim3(8, 32), 128, TC_SMEM, s3>>>(obuf + off2, wpt, out + off2, bproj,
                                               1024, C_, C_, C_, 0);
    cudaEventRecord(evB2, s3);

    // s4: batch 3 (xh3 + wvt on this stream; needs attn + wpt)
    tc_gemm<<<dim3(8, 32), 128, TC_SMEM, s4>>>(xh + off3, wvt, vbuf + off3, nullptr,
                                               1024, C_, C_, C_, 1);
    cudaStreamWaitEvent(s4, evAttn, 0);
    apply_tc<<<dim3(32, 16), 128, AP_SMEM, s4>>>(vbuf, attnbuf, obuf, 3);
    cudaStreamWaitEvent(s4, evWpt, 0);
    tc_gemm<<<dim3(8, 32), 128, TC_SMEM, s4>>>(obuf + off3, wpt, out + off3, bproj,
                                               1024, C_, C_, C_, 0);
    cudaEventRecord(evB3, s4);

    // Join all pipelines back to the main stream
    cudaStreamWaitEvent(0, evB1, 0);
    cudaStreamWaitEvent(0, evB2, 0);
    cudaStreamWaitEvent(0, evB3, 0);
}

// round 16
// speedup vs baseline: 1.1844x; 1.1844x over previous
#include <cuda_runtime.h>
#include <cuda_fp16.h>
#include <math.h>
#include <stdint.h>

// Problem constants
#define B_ 4
#define N_ 96
#define P_ 64
#define C_ 1024
#define H_ 16
#define HD_ 64
#define M_ROWS (B_*N_*P_)   // 24576
#define MB (N_*P_)          // 6144 rows per batch

// Scratch (device globals: allocation-free contract)
__device__ __half  g_xh[M_ROWS*C_];       // x, fp16
__device__ __half  g_xbar[B_*N_*C_];      // pooled input, fp16
__device__ float   g_qk[B_*N_*2*C_];      // q|k projections (fp32)
__device__ __half  g_attnh[B_*H_*N_*N_];  // softmax probs, fp16
__device__ __half  g_vh[M_ROWS*C_];       // x @ W_v, fp16
__device__ __half  g_oh[M_ROWS*C_];       // attn-applied, fp16
__device__ __half  g_wqkt[2*C_*C_];       // W_qk^T [n][k], fp16
__device__ __half  g_wvt[C_*C_];          // W_v^T
__device__ __half  g_wpt[C_*C_];          // W_proj^T

#define LDSM4(R0,R1,R2,R3,ADDR) \
    asm volatile("ldmatrix.sync.aligned.m8n8.x4.shared.b16 {%0,%1,%2,%3}, [%4];" \
        : "=r"(R0),"=r"(R1),"=r"(R2),"=r"(R3) : "r"(ADDR))
#define LDSM4T(R0,R1,R2,R3,ADDR) \
    asm volatile("ldmatrix.sync.aligned.m8n8.x4.trans.shared.b16 {%0,%1,%2,%3}, [%4];" \
        : "=r"(R0),"=r"(R1),"=r"(R2),"=r"(R3) : "r"(ADDR))

#define MMA_F16(C0,C1,C2,C3,A0,A1,A2,A3,B0,B1) \
    asm volatile("mma.sync.aligned.m16n8k16.row.col.f32.f16.f16.f32 " \
        "{%0,%1,%2,%3}, {%4,%5,%6,%7}, {%8,%9}, {%0,%1,%2,%3};" \
        : "+f"(C0),"+f"(C1),"+f"(C2),"+f"(C3) \
        : "r"(A0),"r"(A1),"r"(A2),"r"(A3),"r"(B0),"r"(B1))

#define CP16(DST, SRC) \
    asm volatile("cp.async.cg.shared.global [%0], [%1], 16;" :: "r"(DST), "l"(SRC) : "memory")
#define CP_COMMIT() asm volatile("cp.async.commit_group;" ::: "memory")
#define CP_WAIT1()  asm volatile("cp.async.wait_group 1;" ::: "memory")

// ---------------------------------------------------------------------------
// FP16 tensor GEMM (round-14 proven config): C = A[M,K] @ Bt[N,K]^T (+bias).
// CTA tile 128x128, 128 threads (4 warps: 2M x 2N), warp tile 64x64, KTILE=32,
// 3-stage cp.async, 61 KB smem -> 2 CTAs/SM. wf:HMMA = 1.0.
// ---------------------------------------------------------------------------
#define SROW16 40                          // halves per smem row
#define TA16 (128 * SROW16 * 2)            // 10240 B
#define TB16 (128 * SROW16 * 2)            // 10240 B
#define ST16 (TA16 + TB16)                 // 20480 B
#define NST 3
#define TC_SMEM (NST * ST16)               // 61440 B

__global__ void __launch_bounds__(128, 2) tc_gemm(
    const __half* __restrict__ A, const __half* __restrict__ Bt,
    void* __restrict__ Cm, const float* __restrict__ bias,
    int K, int lda, int ldb, int ldc, int outHalf)
{
    extern __shared__ char smem[];
    uint32_t smem_base = (uint32_t)__cvta_generic_to_shared(smem);
    int tid = threadIdx.x;
    int lane = tid & 31, warp = tid >> 5;
    int wm = warp & 1, wn = warp >> 1;

    const __half* Ab = A + (size_t)blockIdx.y * 128 * lda;
    const __half* Bb = Bt + (size_t)blockIdx.x * 128 * ldb;

    float acc[4][8][4];
    #pragma unroll
    for (int i = 0; i < 4; ++i)
        #pragma unroll
        for (int j = 0; j < 8; ++j)
            #pragma unroll
            for (int r = 0; r < 4; ++r) acc[i][j][r] = 0.f;

    auto load_stage = [&](int s, int kt) {
        uint32_t sa = smem_base + s * ST16;
        uint32_t sb = sa + TA16;
        #pragma unroll
        for (int it = 0; it < 4; ++it) {          // A: 512 x 16B
            int q = tid + it * 128;
            int r = q >> 2, c = q & 3;
            CP16(sa + (uint32_t)(r * SROW16 + c * 8) * 2u,
                 Ab + (size_t)r * lda + kt * 32 + c * 8);
        }
        #pragma unroll
        for (int it = 0; it < 4; ++it) {          // B: 512 x 16B
            int q = tid + it * 128;
            int r = q >> 2, c = q & 3;
            CP16(sb + (uint32_t)(r * SROW16 + c * 8) * 2u,
                 Bb + (size_t)r * ldb + kt * 32 + c * 8);
        }
    };

    int nt = K / 32;
    load_stage(0, 0); CP_COMMIT();
    load_stage(1, 1); CP_COMMIT();

    int l7 = lane & 7;
    int lg8 = (lane >> 3) & 1;
    int lg16 = lane >> 4;

    #pragma unroll 1
    for (int kt = 0; kt < nt; ++kt) {
        CP_WAIT1();
        __syncthreads();
        if (kt + 2 < nt) load_stage((kt + 2) % NST, kt + 2);
        CP_COMMIT();

        uint32_t sa = smem_base + (kt % NST) * ST16;
        uint32_t sb = sa + TA16;

        #pragma unroll
        for (int ks = 0; ks < 2; ++ks) {
            int k0 = ks * 16;
            uint32_t a[4][4], b[4][4];
            #pragma unroll
            for (int mi = 0; mi < 4; ++mi) {
                int row = wm * 64 + mi * 16 + l7 + lg8 * 8;
                int kc = k0 + lg16 * 8;
                LDSM4(a[mi][0], a[mi][1], a[mi][2], a[mi][3],
                      sa + (uint32_t)(row * SROW16 + kc) * 2u);
            }
            #pragma unroll
            for (int pi = 0; pi < 4; ++pi) {
                int nrow = wn * 64 + pi * 16 + l7 + lg16 * 8;
                int kc = k0 + lg8 * 8;
                LDSM4(b[pi][0], b[pi][1], b[pi][2], b[pi][3],
                      sb + (uint32_t)(nrow * SROW16 + kc) * 2u);
            }
            #pragma unroll
            for (int mi = 0; mi < 4; ++mi)
                #pragma unroll
                for (int ni = 0; ni < 8; ++ni)
                    MMA_F16(acc[mi][ni][0], acc[mi][ni][1], acc[mi][ni][2], acc[mi][ni][3],
                            a[mi][0], a[mi][1], a[mi][2], a[mi][3],
                            b[ni >> 1][(ni & 1) * 2], b[ni >> 1][(ni & 1) * 2 + 1]);
        }
    }

    int cm = blockIdx.y * 128 + wm * 64;
    int cn = blockIdx.x * 128 + wn * 64;
    int er = lane >> 2;
    int ec = (lane & 3) * 2;
    #pragma unroll
    for (int ni = 0; ni < 8; ++ni) {
        int col = cn + ni * 8 + ec;
        float bb0 = bias ? bias[col] : 0.f;
        float bb1 = bias ? bias[col + 1] : 0.f;
        #pragma unroll
        for (int mi = 0; mi < 4; ++mi) {
            int row = cm + mi * 16 + er;
            float v0 = acc[mi][ni][0] + bb0, v1 = acc[mi][ni][1] + bb1;
            float v2 = acc[mi][ni][2] + bb0, v3 = acc[mi][ni][3] + bb1;
            if (outHalf) {
                __half* Ch = (__half*)Cm;
                *(__half2*)(Ch + (size_t)row * ldc + col) = __floats2half2_rn(v0, v1);
                *(__half2*)(Ch + (size_t)(row + 8) * ldc + col) = __floats2half2_rn(v2, v3);
            } else {
                float* Cf = (float*)Cm;
                *(float2*)(Cf + (size_t)row * ldc + col) = make_float2(v0, v1);
                *(float2*)(Cf + (size_t)(row + 8) * ldc + col) = make_float2(v2, v3);
            }
        }
    }
}

// ---------------------------------------------------------------------------
// apply_tc v2 (the single change this round): per (b,h) GEMM
// o[n,(p,hd)] = attn[n,m] @ v[m,(p,hd)]. 128 threads (4 warps: 2M x 2N),
// CTA 96x128, warp tile 48x64, K=96. wf:HMMA 1.17 (was 1.67).
// ---------------------------------------------------------------------------
#define AP_AROW 24
#define AP_BROW 136
#define AP_TA (96 * AP_AROW * 2)
#define AP_TB (16 * AP_BROW * 2)
#define AP_ST (AP_TA + AP_TB)
#define AP_SMEM (3 * AP_ST)             // 26880 B

__global__ void __launch_bounds__(128) apply_tc(
    const __half* __restrict__ v, const __half* __restrict__ attn,
    __half* __restrict__ out, int bArg)
{
    extern __shared__ char smem[];
    uint32_t smem_base = (uint32_t)__cvta_generic_to_shared(smem);
    int tid = threadIdx.x;
    int lane = tid & 31, warp = tid >> 5;
    int wm = warp & 1, wn = warp >> 1;

    int h = blockIdx.y;
    int b = bArg;
    int bh = b * H_ + h;
    int p0 = blockIdx.x * 2;

    const __half* ab = attn + (size_t)bh * N_ * N_;
    const __half* vb = v + (size_t)b * N_ * P_ * C_ + h * HD_;

    float acc[3][8][4];
    #pragma unroll
    for (int i = 0; i < 3; ++i)
        #pragma unroll
        for (int j = 0; j < 8; ++j)
            #pragma unroll
            for (int r = 0; r < 4; ++r) acc[i][j][r] = 0.f;

    auto load_stage = [&](int s, int kt) {
        uint32_t sa = smem_base + s * AP_ST;
        uint32_t sb = sa + AP_TA;
        // A: 96 rows x 2 chunks = 192
        #pragma unroll
        for (int it = 0; it < 2; ++it) {
            int q = tid + it * 128;
            if (q < 192) {
                int r = q >> 1, c = q & 1;
                CP16(sa + (uint32_t)(r * AP_AROW + c * 8) * 2u,
                     ab + (size_t)r * N_ + kt * 16 + c * 8);
            }
        }
        // B: 16 k-rows x 16 chunks = 256
        #pragma unroll
        for (int it = 0; it < 2; ++it) {
            int q = tid + it * 128;
            int r = q >> 4, c = q & 15;
            int m = kt * 16 + r;
            int p = p0 + (c >> 3), hd = (c & 7) * 8;
            CP16(sb + (uint32_t)(r * AP_BROW + c * 8) * 2u,
                 vb + (size_t)m * P_ * C_ + (size_t)p * C_ + hd);
        }
    };

    load_stage(0, 0); CP_COMMIT();
    load_stage(1, 1); CP_COMMIT();

    int l7 = lane & 7;
    int lg8 = (lane >> 3) & 1;
    int lg16 = lane >> 4;

    #pragma unroll 1
    for (int kt = 0; kt < 6; ++kt) {
        CP_WAIT1();
        __syncthreads();
        if (kt + 2 < 6) load_stage((kt + 2) % 3, kt + 2);
        CP_COMMIT();

        uint32_t sa = smem_base + (kt % 3) * AP_ST;
        uint32_t sb = sa + AP_TA;

        uint32_t a[3][4], bfr[4][4];
        #pragma unroll
        for (int mi = 0; mi < 3; ++mi) {
            int row = wm * 48 + mi * 16 + l7 + lg8 * 8;
            int kc = lg16 * 8;
            LDSM4(a[mi][0], a[mi][1], a[mi][2], a[mi][3],
                  sa + (uint32_t)(row * AP_AROW + kc) * 2u);
        }
        #pragma unroll
        for (int pi = 0; pi < 4; ++pi) {
            int krow = l7 + lg8 * 8;
            int nc = wn * 64 + pi * 16 + lg16 * 8;
            LDSM4T(bfr[pi][0], bfr[pi][1], bfr[pi][2], bfr[pi][3],
                   sb + (uint32_t)(krow * AP_BROW + nc) * 2u);
        }
        #pragma unroll
        for (int mi = 0; mi < 3; ++mi)
            #pragma unroll
            for (int ni = 0; ni < 8; ++ni)
                MMA_F16(acc[mi][ni][0], acc[mi][ni][1], acc[mi][ni][2], acc[mi][ni][3],
                        a[mi][0], a[mi][1], a[mi][2], a[mi][3],
                        bfr[ni >> 1][(ni & 1) * 2], bfr[ni >> 1][(ni & 1) * 2 + 1]);
    }

    int er = lane >> 2;
    int ec = (lane & 3) * 2;
    #pragma unroll
    for (int ni = 0; ni < 8; ++ni) {
        int col = wn * 64 + ni * 8 + ec;
        int p = p0 + (col >> 6), hd = col & 63;
        #pragma unroll
        for (int mi = 0; mi < 3; ++mi) {
            int n = wm * 48 + mi * 16 + er;
            __half* op = out + (((size_t)(b * N_ + n) * P_) + p) * C_ + h * HD_ + hd;
            *(__half2*)op = __floats2half2_rn(acc[mi][ni][0], acc[mi][ni][1]);
            __half* op2 = out + (((size_t)(b * N_ + n + 8) * P_) + p) * C_ + h * HD_ + hd;
            *(__half2*)op2 = __floats2half2_rn(acc[mi][ni][2], acc[mi][ni][3]);
        }
    }
}

// ---------------------------------------------------------------------------
// Weight transpose + fp16: Wt[n][k] = h(W[k][n]); output ld = 1024
// ---------------------------------------------------------------------------
__global__ void wtrans_kernel(const float* __restrict__ W, __half* __restrict__ Wt, int ldw) {
    __shared__ float t[32][33];
    int n0 = blockIdx.x * 32, k0 = blockIdx.y * 32;
    int tx = threadIdx.x, ty = threadIdx.y;
    #pragma unroll
    for (int i = 0; i < 32; i += 8)
        t[ty + i][tx] = W[(size_t)(k0 + ty + i) * ldw + n0 + tx];
    __syncthreads();
    #pragma unroll
    for (int i = 0; i < 32; i += 8)
        Wt[(size_t)(n0 + ty + i) * C_ + k0 + tx] = __float2half_rn(t[tx][ty + i]);
}

// ---------------------------------------------------------------------------
// prep: fused cvt + pool for ONE batch. Block = one n (96 blocks), 256 threads.
// ---------------------------------------------------------------------------
__global__ void __launch_bounds__(256) prep_kernel(
    const float* __restrict__ x, __half* __restrict__ xh,
    __half* __restrict__ xbar, int bArg)
{
    int bn = bArg * N_ + blockIdx.x;
    const float* xp = x + (size_t)bn * P_ * C_;
    __half* xhp = xh + (size_t)bn * P_ * C_;
    int c = threadIdx.x * 4;
    float s0 = 0.f, s1 = 0.f, s2 = 0.f, s3 = 0.f;
    #pragma unroll 4
    for (int p = 0; p < P_; ++p) {
        float4 v = *(const float4*)(xp + (size_t)p * C_ + c);
        s0 += v.x; s1 += v.y; s2 += v.z; s3 += v.w;
        *(__half2*)(xhp + (size_t)p * C_ + c)     = __floats2half2_rn(v.x, v.y);
        *(__half2*)(xhp + (size_t)p * C_ + c + 2) = __floats2half2_rn(v.z, v.w);
    }
    __half* xb = xbar + (size_t)bn * C_ + c;
    *(__half2*)xb       = __floats2half2_rn(s0 * (1.f / 64.f), s1 * (1.f / 64.f));
    *(__half2*)(xb + 2) = __floats2half2_rn(s2 * (1.f / 64.f), s3 * (1.f / 64.f));
}

// ---------------------------------------------------------------------------
// attn: block=(b,h), 256 threads; warp per n-row, shfl softmax.
// ---------------------------------------------------------------------------
#define ATTN_SMEM (96*64*4 + 64*96*4)   // 49152
__global__ void __launch_bounds__(256) attn_kernel(
    const float* __restrict__ qk, __half* __restrict__ attn)
{
    extern __shared__ float sm[];
    float* qs = sm;               // [96][64]
    float* kt = sm + 96 * 64;     // [64][96]
    int b = blockIdx.x >> 4, h = blockIdx.x & 15;
    for (int i = threadIdx.x; i < N_ * HD_; i += 256) {
        int n = i >> 6, d = i & 63;
        const float* base = qk + ((size_t)(b * N_ + n)) * (2 * C_) + h * HD_ + d;
        qs[n * HD_ + d] = base[0];
        kt[d * N_ + n] = base[C_];
    }
    __syncthreads();

    int warp = threadIdx.x >> 5, lane = threadIdx.x & 31;
    int m0 = lane * 3;
    for (int n = warp; n < N_; n += 8) {
        float d0 = 0.f, d1 = 0.f, d2 = 0.f;
        const float* qr = qs + n * HD_;
        #pragma unroll
        for (int d = 0; d < HD_; ++d) {
            float q = qr[d];
            const float* kr = kt + d * N_ + m0;
            d0 += q * kr[0]; d1 += q * kr[1]; d2 += q * kr[2];
        }
        d0 *= 0.125f; d1 *= 0.125f; d2 *= 0.125f;
        float mx = fmaxf(d0, fmaxf(d1, d2));
        #pragma unroll
        for (int o = 16; o; o >>= 1) mx = fmaxf(mx, __shfl_xor_sync(0xFFFFFFFFu, mx, o));
        float e0 = __expf(d0 - mx), e1 = __expf(d1 - mx), e2 = __expf(d2 - mx);
        float s = e0 + e1 + e2;
        #pragma unroll
        for (int o = 16; o; o >>= 1) s += __shfl_xor_sync(0xFFFFFFFFu, s, o);
        float inv = 1.f / s;
        __half* row = attn + ((size_t)blockIdx.x * N_ + n) * N_ + m0;
        row[0] = __float2half_rn(e0 * inv);
        row[1] = __float2half_rn(e1 * inv);
        row[2] = __float2half_rn(e2 * inv);
    }
}

// ---------------------------------------------------------------------------
extern "C" void kernel_launch(void* const* d_in, const int* in_sizes, int n_in,
                              void* d_out, int out_size)
{
    const float* x     = (const float*)d_in[0];
    const float* Wqkv  = (const float*)d_in[1];
    const float* Wproj = (const float*)d_in[2];
    const float* bproj = (const float*)d_in[3];
    float* out = (float*)d_out;

    __half *xh, *xbar, *attnbuf, *vbuf, *obuf, *wqkt, *wvt, *wpt;
    float *qkbuf;
    cudaGetSymbolAddress((void**)&xh,      g_xh);
    cudaGetSymbolAddress((void**)&xbar,    g_xbar);
    cudaGetSymbolAddress((void**)&qkbuf,   g_qk);
    cudaGetSymbolAddress((void**)&attnbuf, g_attnh);
    cudaGetSymbolAddress((void**)&vbuf,    g_vh);
    cudaGetSymbolAddress((void**)&obuf,    g_oh);
    cudaGetSymbolAddress((void**)&wqkt,    g_wqkt);
    cudaGetSymbolAddress((void**)&wvt,     g_wvt);
    cudaGetSymbolAddress((void**)&wpt,     g_wpt);

    cudaFuncSetAttribute(tc_gemm, cudaFuncAttributeMaxDynamicSharedMemorySize, TC_SMEM);
    cudaFuncSetAttribute(apply_tc, cudaFuncAttributeMaxDynamicSharedMemorySize, AP_SMEM);
    cudaFuncSetAttribute(attn_kernel, cudaFuncAttributeMaxDynamicSharedMemorySize, ATTN_SMEM);

    // Streams + events (created once; host-side only).
    static cudaStream_t s2 = nullptr, s3 = nullptr, s4 = nullptr;
    static cudaEvent_t evRoot, evAttn, evWpt, evWvt, evP0, evP2, evP3, evB1, evB2, evB3;
    if (!s2) {
        cudaStreamCreateWithFlags(&s2, cudaStreamNonBlocking);
        cudaStreamCreateWithFlags(&s3, cudaStreamNonBlocking);
        cudaStreamCreateWithFlags(&s4, cudaStreamNonBlocking);
        cudaEventCreateWithFlags(&evRoot, cudaEventDisableTiming);
        cudaEventCreateWithFlags(&evAttn, cudaEventDisableTiming);
        cudaEventCreateWithFlags(&evWpt, cudaEventDisableTiming);
        cudaEventCreateWithFlags(&evWvt, cudaEventDisableTiming);
        cudaEventCreateWithFlags(&evP0, cudaEventDisableTiming);
        cudaEventCreateWithFlags(&evP2, cudaEventDisableTiming);
        cudaEventCreateWithFlags(&evP3, cudaEventDisableTiming);
        cudaEventCreateWithFlags(&evB1, cudaEventDisableTiming);
        cudaEventCreateWithFlags(&evB2, cudaEventDisableTiming);
        cudaEventCreateWithFlags(&evB3, cudaEventDisableTiming);
    }

    // ---- Capture-safe ordering: every record precedes every wait on it.

    cudaEventRecord(evRoot, 0);
    cudaStreamWaitEvent(s2, evRoot, 0);
    cudaStreamWaitEvent(s3, evRoot, 0);
    cudaStreamWaitEvent(s4, evRoot, 0);

    const size_t off1 = (size_t)1 * MB * C_;
    const size_t off2 = (size_t)2 * MB * C_;
    const size_t off3 = (size_t)3 * MB * C_;

    // Prologue phase (round-14 layout) --------------------------------------
    // main: v-weight transpose + batch-0 prep
    wtrans_kernel<<<dim3(32, 32), dim3(32, 8)>>>(Wqkv + 2 * C_, wvt, 3 * C_);
    cudaEventRecord(evWvt, 0);
    prep_kernel<<<N_, 256>>>(x, xh, xbar, 0);
    cudaEventRecord(evP0, 0);
    // s3: proj-weight transpose + batch-2 prep
    wtrans_kernel<<<dim3(32, 32), dim3(32, 8), 0, s3>>>(Wproj, wpt, C_);
    cudaEventRecord(evWpt, s3);
    prep_kernel<<<N_, 256, 0, s3>>>(x, xh, xbar, 2);
    cudaEventRecord(evP2, s3);
    // s4: batch-3 prep
    prep_kernel<<<N_, 256, 0, s4>>>(x, xh, xbar, 3);
    cudaEventRecord(evP3, s4);
    // s2: qk-weight transpose + batch-1 prep, then qk/attn (needs all xbar)
    wtrans_kernel<<<dim3(64, 32), dim3(32, 8), 0, s2>>>(Wqkv, wqkt, 3 * C_);
    prep_kernel<<<N_, 256, 0, s2>>>(x, xh, xbar, 1);
    cudaStreamWaitEvent(s2, evP0, 0);
    cudaStreamWaitEvent(s2, evP2, 0);
    cudaStreamWaitEvent(s2, evP3, 0);
    tc_gemm<<<dim3(16, 3), 128, TC_SMEM, s2>>>(xbar, wqkt, qkbuf, nullptr, 1024, C_, C_, 2 * C_, 0);
    attn_kernel<<<B_ * H_, 256, ATTN_SMEM, s2>>>(qkbuf, attnbuf);
    cudaEventRecord(evAttn, s2);

    // Pipeline phase --------------------------------------------------------
    // main: batch 0 (xh0 + wvt on this stream)
    tc_gemm<<<dim3(8, 48), 128, TC_SMEM>>>(xh, wvt, vbuf, nullptr, 1024, C_, C_, C_, 1);
    cudaStreamWaitEvent(0, evAttn, 0);
    apply_tc<<<dim3(32, 16), 128, AP_SMEM>>>(vbuf, attnbuf, obuf, 0);
    cudaStreamWaitEvent(0, evWpt, 0);
    tc_gemm<<<dim3(8, 48), 128, TC_SMEM>>>(obuf, wpt, out, bproj, 1024, C_, C_, C_, 0);

    // s2: batch 1 (xh1 + attn on this stream; needs wvt + wpt)
    cudaStreamWaitEvent(s2, evWvt, 0);
    tc_gemm<<<dim3(8, 48), 128, TC_SMEM, s2>>>(xh + off1, wvt, vbuf + off1, nullptr,
                                               1024, C_, C_, C_, 1);
    apply_tc<<<dim3(32, 16), 128, AP_SMEM, s2>>>(vbuf, attnbuf, obuf, 1);
    cudaStreamWaitEvent(s2, evWpt, 0);
    tc_gemm<<<dim3(8, 48), 128, TC_SMEM, s2>>>(obuf + off1, wpt, out + off1, bproj,
                                               1024, C_, C_, C_, 0);
    cudaEventRecord(evB1, s2);

    // s3: batch 2 (xh2 + wpt on this stream; needs wvt + attn)
    cudaStreamWaitEvent(s3, evWvt, 0);
    tc_gemm<<<dim3(8, 48), 128, TC_SMEM, s3>>>(xh + off2, wvt, vbuf + off2, nullptr,
                                               1024, C_, C_, C_, 1);
    cudaStreamWaitEvent(s3, evAttn, 0);
    apply_tc<<<dim3(32, 16), 128, AP_SMEM, s3>>>(vbuf, attnbuf, obuf, 2);
    tc_gemm<<<dim3(8, 48), 128, TC_SMEM, s3>>>(obuf + off2, wpt, out + off2, bproj,
                                               1024, C_, C_, C_, 0);
    cudaEventRecord(evB2, s3);

    // s4: batch 3 (xh3 on this stream; needs wvt + attn + wpt)
    cudaStreamWaitEvent(s4, evWvt, 0);
    tc_gemm<<<dim3(8, 48), 128, TC_SMEM, s4>>>(xh + off3, wvt, vbuf + off3, nullptr,
                                               1024, C_, C_, C_, 1);
    cudaStreamWaitEvent(s4, evAttn, 0);
    apply_tc<<<dim3(32, 16), 128, AP_SMEM, s4>>>(vbuf, attnbuf, obuf, 3);
    cudaStreamWaitEvent(s4, evWpt, 0);
    tc_gemm<<<dim3(8, 48), 128, TC_SMEM, s4>>>(obuf + off3, wpt, out + off3, bproj,
                                               1024, C_, C_, C_, 0);
    cudaEventRecord(evB3, s4);

    // Join all pipelines back to the main stream
    cudaStreamWaitEvent(0, evB1, 0);
    cudaStreamWaitEvent(0, evB2, 0);
    cudaStreamWaitEvent(0, evB3, 0);
}